// round 3
// baseline (speedup 1.0000x reference)
#include <cuda_runtime.h>

#define BDIM 64
#define TDIM 512
#define INDIM 128
#define HDIM 512
#define G3 (3*HDIM)

#define WPITCH 520   // 48 W rows, pitch pad: conflict-free + 16B aligned
#define HPITCH 516   // 16 h rows: 4*HPITCH = 16 mod 32 banks -> bg lanes split halves
#define SMEM_SCAN ((48*WPITCH + 16*HPITCH)*4)   // 99840 + 33024 = 132864 B

// Static device scratch (no runtime allocation anywhere)
__device__ float g_xg[(size_t)BDIM * TDIM * G3];     // [B,T,3H] gate pre-activations
__device__ float g_hseq[(size_t)BDIM * TDIM * HDIM]; // layer-0 hidden sequence
__device__ float g_h[2][BDIM * HDIM];                // ping-pong hidden state
__device__ unsigned g_bar[4];                        // per-b-tile barrier counters

typedef unsigned long long ull;

__device__ __forceinline__ void fma2(ull &d, ull a, ull b) {
    asm("fma.rn.f32x2 %0, %1, %2, %0;" : "+l"(d) : "l"(a), "l"(b));
}
__device__ __forceinline__ float ull_sum(ull a) {
    union { ull u; float2 f; } c; c.u = a; return c.f.x + c.f.y;
}
__device__ __forceinline__ float sigm(float x) { return 1.f / (1.f + __expf(-x)); }

// ---------------------------------------------------------------------------
// Input projection GEMM: C[M,1536] = A[M,K] @ W[1536,K]^T + bias
// Block tile 128x64, BK=32, 256 threads, 8x4 micro-tile, f32x2 K-pair FMAs.
// ---------------------------------------------------------------------------
template<int K>
__global__ void __launch_bounds__(256) proj_kernel(const float* __restrict__ A,
                                                   const float* __restrict__ W,
                                                   const float* __restrict__ bias,
                                                   float* __restrict__ C)
{
    __shared__ float As[128 * 34];
    __shared__ float Bs[64 * 34];
    const int m0 = blockIdx.x * 128;
    const int n0 = blockIdx.y * 64;
    const int tid = threadIdx.x;
    const int tx = tid & 15;   // N direction (4 cols each)
    const int ty = tid >> 4;   // M direction (8 rows each)

    ull acc[8][4];
    #pragma unroll
    for (int i = 0; i < 8; i++)
        #pragma unroll
        for (int j = 0; j < 4; j++) acc[i][j] = 0ull;

    for (int kt = 0; kt < K; kt += 32) {
        __syncthreads();
        for (int i = tid; i < 1024; i += 256) {
            int row = i >> 3, c4 = i & 7;
            float4 v = *(const float4*)&A[(size_t)(m0 + row) * K + kt + c4 * 4];
            float* d = &As[row * 34 + c4 * 4];
            *(float2*)(d)     = make_float2(v.x, v.y);
            *(float2*)(d + 2) = make_float2(v.z, v.w);
        }
        for (int i = tid; i < 512; i += 256) {
            int row = i >> 3, c4 = i & 7;
            float4 v = *(const float4*)&W[(size_t)(n0 + row) * K + kt + c4 * 4];
            float* d = &Bs[row * 34 + c4 * 4];
            *(float2*)(d)     = make_float2(v.x, v.y);
            *(float2*)(d + 2) = make_float2(v.z, v.w);
        }
        __syncthreads();

        #pragma unroll
        for (int k2 = 0; k2 < 16; k2++) {
            ull a2[8], b2[4];
            #pragma unroll
            for (int i = 0; i < 8; i++)
                a2[i] = *(const ull*)&As[(ty * 8 + i) * 34 + k2 * 2];
            #pragma unroll
            for (int j = 0; j < 4; j++)
                b2[j] = *(const ull*)&Bs[(tx * 4 + j) * 34 + k2 * 2];
            #pragma unroll
            for (int i = 0; i < 8; i++)
                #pragma unroll
                for (int j = 0; j < 4; j++)
                    fma2(acc[i][j], a2[i], b2[j]);
        }
    }

    #pragma unroll
    for (int i = 0; i < 8; i++) {
        int m = m0 + ty * 8 + i;
        #pragma unroll
        for (int j = 0; j < 4; j++) {
            int n = n0 + tx * 4 + j;
            C[(size_t)m * G3 + n] = ull_sum(acc[i][j]) + bias[n];
        }
    }
}

// ---------------------------------------------------------------------------
// Persistent GRU scan: one launch runs all 512 timesteps of a layer.
// Grid (32 k-tiles, 4 b-tiles), 256 threads, all 128 blocks resident.
// W_hh tile (48x512) staged in smem ONCE. Per step: stage 16x512 h tile,
// register-blocked dots (2k x 3g x 4b per thread, j-slice of 8),
// shfl butterfly reduction, gate math (1 cell/lane), inter-block barrier
// per b-tile group (32 blocks each).
// ---------------------------------------------------------------------------
template<bool WRITE_SEQ>
__global__ void __launch_bounds__(256, 1) scan_kernel(
    const float* __restrict__ W_hh, const float* __restrict__ b_hh,
    const float* __restrict__ xg, float* __restrict__ h0buf,
    float* __restrict__ h1buf, float* __restrict__ h_seq)
{
    extern __shared__ float smem[];
    float* sW = smem;                 // 48 rows x 512 (pitch WPITCH)
    float* sH = smem + 48 * WPITCH;   // 16 rows x 512 (pitch HPITCH)

    const int tid = threadIdx.x;
    const int k0 = blockIdx.x * 16;
    const int b0 = blockIdx.y * 16;

    // Stage W_hh once (rows 0-15: r, 16-31: z, 32-47: n)
    for (int i = tid; i < 48 * 128; i += 256) {
        int row = i >> 7, c4 = i & 127;
        int g = row >> 4, r = row & 15;
        *(float4*)&sW[row * WPITCH + c4 * 4] =
            *(const float4*)&W_hh[(size_t)(g * HDIM + k0 + r) * HDIM + c4 * 4];
    }

    const int kk = (tid >> 5) * 2;   // local k pair base (0,2,...,14)
    const int bg = (tid >> 3) & 3;   // batch quad
    const int jg = tid & 7;          // j slice (round-robin chunks)

    // epilogue cell owned by this lane
    const int kl = kk + (jg & 1);
    const int bl = bg * 4 + (jg >> 1);
    const int kg = k0 + kl;
    const int bgl = b0 + bl;

    const float bhr = b_hh[kg];
    const float bhz = b_hh[HDIM + kg];
    const float bhn = b_hh[2 * HDIM + kg];
    const float* xgb = xg + (size_t)bgl * TDIM * G3 + kg;

    const float* wp[2][3];
    #pragma unroll
    for (int i = 0; i < 2; i++)
        #pragma unroll
        for (int g = 0; g < 3; g++)
            wp[i][g] = &sW[(g * 16 + kk + i) * WPITCH + 2 * jg];
    const float* hp[4];
    #pragma unroll
    for (int i = 0; i < 4; i++)
        hp[i] = &sH[(bg * 4 + i) * HPITCH + 2 * jg];

    for (int t = 0; t < TDIM; t++) {
        const float* hprev = (t & 1) ? h1buf : h0buf;
        float* hnext = (t & 1) ? h0buf : h1buf;

        // stage h tile (L2, bypass L1)
        for (int i = tid; i < 2048; i += 256) {
            int row = i >> 7, c4 = i & 127;
            float4 v = __ldcg((const float4*)&hprev[(size_t)(b0 + row) * HDIM + c4 * 4]);
            *(float4*)&sH[row * HPITCH + c4 * 4] = v;
        }
        __syncthreads();

        // prefetch this cell's precomputed input gates
        const float* xt = xgb + (size_t)t * G3;
        float xr = __ldcg(xt);
        float xz = __ldcg(xt + HDIM);
        float xn = __ldcg(xt + 2 * HDIM);

        ull acc[2][3][4];
        #pragma unroll
        for (int i = 0; i < 2; i++)
            #pragma unroll
            for (int g = 0; g < 3; g++)
                #pragma unroll
                for (int b = 0; b < 4; b++) acc[i][g][b] = 0ull;

        #pragma unroll 4
        for (int jc = 0; jc < 32; jc++) {
            const int off = jc * 16;
            ull h2[4];
            #pragma unroll
            for (int b = 0; b < 4; b++)
                h2[b] = *(const ull*)(hp[b] + off);
            #pragma unroll
            for (int i = 0; i < 2; i++)
                #pragma unroll
                for (int g = 0; g < 3; g++) {
                    ull w2 = *(const ull*)(wp[i][g] + off);
                    #pragma unroll
                    for (int b = 0; b < 4; b++)
                        fma2(acc[i][g][b], h2[b], w2);
                }
        }

        // butterfly-reduce the 8 j-slices (all lanes end with full sums)
        float v[24];
        #pragma unroll
        for (int i = 0; i < 2; i++)
            #pragma unroll
            for (int g = 0; g < 3; g++)
                #pragma unroll
                for (int b = 0; b < 4; b++)
                    v[(i * 3 + g) * 4 + b] = ull_sum(acc[i][g][b]);
        #pragma unroll
        for (int m = 1; m < 8; m <<= 1)
            #pragma unroll
            for (int q = 0; q < 24; q++)
                v[q] += __shfl_xor_sync(0xffffffffu, v[q], m);

        // this lane's cell
        const int ii = jg & 1, bb = jg >> 1;
        float sr = v[(ii * 3 + 0) * 4 + bb];
        float sz = v[(ii * 3 + 1) * 4 + bb];
        float sn = v[(ii * 3 + 2) * 4 + bb];

        float r = sigm(xr + sr + bhr);
        float z = sigm(xz + sz + bhz);
        float n = tanhf(xn + r * (sn + bhn));
        float hold = sH[bl * HPITCH + kg];
        float hnew = (1.f - z) * n + z * hold;

        __stcg(&hnext[(size_t)bgl * HDIM + kg], hnew);
        if (WRITE_SEQ)
            __stcg(&h_seq[((size_t)bgl * TDIM + t) * HDIM + kg], hnew);

        // inter-block barrier within this b-tile group (32 blocks)
        __threadfence();
        __syncthreads();
        if (tid == 0) {
            atomicAdd(&g_bar[blockIdx.y], 1u);
            const unsigned target = 32u * (unsigned)(t + 1);
            while (*(volatile unsigned*)&g_bar[blockIdx.y] < target) { }
            __threadfence();
        }
        __syncthreads();
    }
}

// ---------------------------------------------------------------------------
__global__ void init_kernel(float* h) {
    int i = blockIdx.x * blockDim.x + threadIdx.x;
    h[i] = 0.f;                       // zeros both ping-pong buffers (2*64*512)
    if (i < 4) g_bar[i] = 0u;
}

__global__ void fc_kernel(const float* __restrict__ h, const float* __restrict__ W,
                          const float* __restrict__ bias, float* __restrict__ out)
{
    const int b = blockIdx.x;
    float s = 0.f;
    for (int k = threadIdx.x; k < HDIM; k += 128)
        s += h[(size_t)b * HDIM + k] * W[k];
    __shared__ float red[128];
    red[threadIdx.x] = s; __syncthreads();
    for (int off = 64; off > 0; off >>= 1) {
        if (threadIdx.x < off) red[threadIdx.x] += red[threadIdx.x + off];
        __syncthreads();
    }
    if (threadIdx.x == 0) out[b] = red[0] + bias[0];
}

// ---------------------------------------------------------------------------
extern "C" void kernel_launch(void* const* d_in, const int* in_sizes, int n_in,
                              void* d_out, int out_size)
{
    const float* X     = (const float*)d_in[0];
    const float* W_ih0 = (const float*)d_in[1];
    const float* W_hh0 = (const float*)d_in[2];
    const float* b_ih0 = (const float*)d_in[3];
    const float* b_hh0 = (const float*)d_in[4];
    const float* W_ih1 = (const float*)d_in[5];
    const float* W_hh1 = (const float*)d_in[6];
    const float* b_ih1 = (const float*)d_in[7];
    const float* b_hh1 = (const float*)d_in[8];
    const float* fc_W  = (const float*)d_in[9];
    const float* fc_b  = (const float*)d_in[10];
    float* out = (float*)d_out;

    float *xg, *hseq, *hbuf;
    cudaGetSymbolAddress((void**)&xg, g_xg);
    cudaGetSymbolAddress((void**)&hseq, g_hseq);
    cudaGetSymbolAddress((void**)&hbuf, g_h);

    cudaFuncSetAttribute(scan_kernel<true>,
                         cudaFuncAttributeMaxDynamicSharedMemorySize, SMEM_SCAN);
    cudaFuncSetAttribute(scan_kernel<false>,
                         cudaFuncAttributeMaxDynamicSharedMemorySize, SMEM_SCAN);

    const dim3 pgrid(BDIM * TDIM / 128, G3 / 64);
    const size_t HB = (size_t)BDIM * HDIM;

    // Layer 0
    proj_kernel<INDIM><<<pgrid, 256>>>(X, W_ih0, b_ih0, xg);
    init_kernel<<<128, 512>>>(hbuf);
    scan_kernel<true><<<dim3(32, 4), 256, SMEM_SCAN>>>(
        W_hh0, b_hh0, xg, hbuf, hbuf + HB, hseq);

    // Layer 1
    proj_kernel<HDIM><<<pgrid, 256>>>(hseq, W_ih1, b_ih1, xg);
    init_kernel<<<128, 512>>>(hbuf);
    scan_kernel<false><<<dim3(32, 4), 256, SMEM_SCAN>>>(
        W_hh1, b_hh1, xg, hbuf, hbuf + HB, nullptr);

    // Final h (after 512 steps) sits in parity-0 buffer
    fc_kernel<<<BDIM, 128>>>(hbuf, fc_W, fc_b, out);
}

// round 4
// speedup vs baseline: 1.3884x; 1.3884x over previous
#include <cuda_runtime.h>

#define BDIM 64
#define TDIM 512
#define INDIM 128
#define HDIM 512
#define G3 (3*HDIM)

#define WPITCH 520   // 48 W rows; 16B-aligned rows
#define HPITCH 518   // 16 h rows; 8*HPITCH ≡ 16 mod 32 banks -> halves split banks
#define SMEM_SCAN ((48*WPITCH + 16*HPITCH)*4)   // 99840 + 33152 = 132992 B

#define PJP 34                                   // proj smem pitch (floats)
#define SMEM_PROJ ((2*128*PJP + 2*64*PJP)*4)     // double-buffered A+B tiles = 52224 B

// Static device scratch (no runtime allocation anywhere)
__device__ float g_xg[(size_t)BDIM * TDIM * G3];     // [B,T,3H] gate pre-activations
__device__ float g_hseq[(size_t)BDIM * TDIM * HDIM]; // layer-0 hidden sequence
__device__ float g_h[2][BDIM * HDIM];                // ping-pong hidden state
__device__ __align__(128) unsigned g_bar[4][32];     // one 128B line per b-group

typedef unsigned long long ull;

__device__ __forceinline__ void fma2(ull &d, ull a, ull b) {
    asm("fma.rn.f32x2 %0, %1, %2, %0;" : "+l"(d) : "l"(a), "l"(b));
}
__device__ __forceinline__ float ull_sum(ull a) {
    union { ull u; float2 f; } c; c.u = a; return c.f.x + c.f.y;
}
__device__ __forceinline__ float sigm(float x) { return 1.f / (1.f + __expf(-x)); }

__device__ __forceinline__ void cp8(float* s, const float* g) {
    unsigned ss = (unsigned)__cvta_generic_to_shared(s);
    asm volatile("cp.async.ca.shared.global [%0], [%1], 8;" :: "r"(ss), "l"(g));
}
__device__ __forceinline__ void cp_commit() {
    asm volatile("cp.async.commit_group;");
}

// ---------------------------------------------------------------------------
// Input projection GEMM: C[M,1536] = A[M,K] @ W[1536,K]^T + bias
// 128x64 tile, BK=32, 256 threads, 8x4 micro-tile, cp.async double buffering.
// ---------------------------------------------------------------------------
template<int K>
__global__ void __launch_bounds__(256) proj_kernel(const float* __restrict__ A,
                                                   const float* __restrict__ W,
                                                   const float* __restrict__ bias,
                                                   float* __restrict__ C)
{
    extern __shared__ float ps[];
    float* AsBase = ps;                 // 2 x (128 x PJP)
    float* BsBase = ps + 2 * 128 * PJP; // 2 x (64 x PJP)
    const int m0 = blockIdx.x * 128;
    const int n0 = blockIdx.y * 64;
    const int tid = threadIdx.x;
    const int tx = tid & 15;   // N direction (4 cols each)
    const int ty = tid >> 4;   // M direction (8 rows each)
    const int NT = K / 32;

    ull acc[8][4];
    #pragma unroll
    for (int i = 0; i < 8; i++)
        #pragma unroll
        for (int j = 0; j < 4; j++) acc[i][j] = 0ull;

    // async stage of tile kt into buffer buf
    auto stage = [&](int kt, int buf) {
        float* Ad = AsBase + buf * 128 * PJP;
        float* Bd = BsBase + buf * 64 * PJP;
        #pragma unroll
        for (int i = tid; i < 1024; i += 256) {
            int row = i >> 3, c4 = i & 7;
            const float* g = &A[(size_t)(m0 + row) * K + kt + c4 * 4];
            float* d = &Ad[row * PJP + c4 * 4];
            cp8(d, g); cp8(d + 2, g + 2);
        }
        #pragma unroll
        for (int i = tid; i < 512; i += 256) {
            int row = i >> 3, c4 = i & 7;
            const float* g = &W[(size_t)(n0 + row) * K + kt + c4 * 4];
            float* d = &Bd[row * PJP + c4 * 4];
            cp8(d, g); cp8(d + 2, g + 2);
        }
        cp_commit();
    };

    stage(0, 0);
    for (int kt = 0; kt < NT; kt++) {
        if (kt + 1 < NT) {
            stage((kt + 1) * 32, (kt + 1) & 1);
            asm volatile("cp.async.wait_group 1;");
        } else {
            asm volatile("cp.async.wait_group 0;");
        }
        __syncthreads();

        const float* As = AsBase + (kt & 1) * 128 * PJP;
        const float* Bs = BsBase + (kt & 1) * 64 * PJP;
        #pragma unroll
        for (int k2 = 0; k2 < 16; k2++) {
            ull a2[8], b2[4];
            #pragma unroll
            for (int i = 0; i < 8; i++)
                a2[i] = *(const ull*)&As[(ty * 8 + i) * PJP + k2 * 2];
            #pragma unroll
            for (int j = 0; j < 4; j++)
                b2[j] = *(const ull*)&Bs[(tx * 4 + j) * PJP + k2 * 2];
            #pragma unroll
            for (int i = 0; i < 8; i++)
                #pragma unroll
                for (int j = 0; j < 4; j++)
                    fma2(acc[i][j], a2[i], b2[j]);
        }
        __syncthreads();
    }

    #pragma unroll
    for (int i = 0; i < 8; i++) {
        int m = m0 + ty * 8 + i;
        #pragma unroll
        for (int j = 0; j < 4; j++) {
            int n = n0 + tx * 4 + j;
            C[(size_t)m * G3 + n] = ull_sum(acc[i][j]) + bias[n];
        }
    }
}

// ---------------------------------------------------------------------------
// Persistent GRU scan. Grid (32 k-tiles, 4 b-groups), 256 threads, all resident.
// W_hh staged in smem once. Per step: stage 16x512 h tile, micro-tile
// 2k x 3g x 8b x 16j per thread (W warp-broadcast), tree-exchange shfl
// reduction, gate math (1 cell/lane), release/acquire inter-block barrier.
// ---------------------------------------------------------------------------
template<bool WRITE_SEQ>
__global__ void __launch_bounds__(256, 1) scan_kernel(
    const float* __restrict__ W_hh, const float* __restrict__ b_hh,
    const float* __restrict__ xg, float* __restrict__ h0buf,
    float* __restrict__ h1buf, float* __restrict__ h_seq)
{
    extern __shared__ float smem[];
    float* sW = smem;                 // 48 rows x 512 (pitch WPITCH)
    float* sH = smem + 48 * WPITCH;   // 16 rows x 512 (pitch HPITCH)

    const int tid = threadIdx.x;
    const int k0 = blockIdx.x * 16;
    const int b0 = blockIdx.y * 16;

    // Stage W_hh once (rows 0-15: r, 16-31: z, 32-47: n)
    for (int i = tid; i < 48 * 128; i += 256) {
        int row = i >> 7, c4 = i & 127;
        int g = row >> 4, r = row & 15;
        *(float4*)&sW[row * WPITCH + c4 * 4] =
            *(const float4*)&W_hh[(size_t)(g * HDIM + k0 + r) * HDIM + c4 * 4];
    }

    const int jg = tid & 15;         // j slice
    const int bg = (tid >> 4) & 1;   // batch half (8 rows)
    const int kk = tid >> 5;         // k pair (warp id)

    // epilogue cell owned by this lane (determined by the exchange tree)
    const int kl = kk * 2 + (jg & 1);
    const int bl = bg * 8 + ((jg >> 1) & 7);
    const int kg = k0 + kl;
    const int bgl = b0 + bl;

    const float bhr = b_hh[kg];
    const float bhz = b_hh[HDIM + kg];
    const float bhn = b_hh[2 * HDIM + kg];
    const float* xgb = xg + (size_t)bgl * TDIM * G3 + kg;

    const float* wp[2][3];
    #pragma unroll
    for (int i = 0; i < 2; i++)
        #pragma unroll
        for (int g = 0; g < 3; g++)
            wp[i][g] = &sW[(g * 16 + kk * 2 + i) * WPITCH + 2 * jg];
    const float* hp[8];
    #pragma unroll
    for (int b = 0; b < 8; b++)
        hp[b] = &sH[(bg * 8 + b) * HPITCH + 2 * jg];

    unsigned* bar = &g_bar[blockIdx.y][0];

    float xr = __ldcg(xgb);
    float xz = __ldcg(xgb + HDIM);
    float xn = __ldcg(xgb + 2 * HDIM);

    for (int t = 0; t < TDIM; t++) {
        const float* hprev = (t & 1) ? h1buf : h0buf;
        float* hnext = (t & 1) ? h0buf : h1buf;

        // stage h tile (gmem float4, smem 2x float2 — 8B-aligned rows)
        #pragma unroll
        for (int i = tid; i < 16 * 128; i += 256) {
            int row = i >> 7, c4 = i & 127;
            float4 v = __ldcg((const float4*)&hprev[(size_t)(b0 + row) * HDIM + c4 * 4]);
            float* d = &sH[row * HPITCH + c4 * 4];
            *(float2*)(d)     = make_float2(v.x, v.y);
            *(float2*)(d + 2) = make_float2(v.z, v.w);
        }
        __syncthreads();

        ull acc[2][3][8];
        #pragma unroll
        for (int i = 0; i < 2; i++)
            #pragma unroll
            for (int g = 0; g < 3; g++)
                #pragma unroll
                for (int b = 0; b < 8; b++) acc[i][g][b] = 0ull;

        #pragma unroll 4
        for (int jc = 0; jc < 16; jc++) {
            const int off = jc * 32;
            ull h2[8];
            #pragma unroll
            for (int b = 0; b < 8; b++)
                h2[b] = *(const ull*)(hp[b] + off);
            #pragma unroll
            for (int i = 0; i < 2; i++)
                #pragma unroll
                for (int g = 0; g < 3; g++) {
                    ull w2 = *(const ull*)(wp[i][g] + off);
                    #pragma unroll
                    for (int b = 0; b < 8; b++)
                        fma2(acc[i][g][b], h2[b], w2);
                }
        }

        // Tree-exchange reduction over the 16 j-slices (45 SHFLs total).
        // Round 1 (xor 8): resolve b bit2 = jg bit3
        float v4[2][3][4];
        {
            const bool hi = (jg >> 3) & 1;
            #pragma unroll
            for (int i = 0; i < 2; i++)
                #pragma unroll
                for (int g = 0; g < 3; g++)
                    #pragma unroll
                    for (int b = 0; b < 4; b++) {
                        float a = ull_sum(acc[i][g][b]);
                        float c = ull_sum(acc[i][g][b + 4]);
                        float send = hi ? a : c;
                        float keep = hi ? c : a;
                        v4[i][g][b] = keep + __shfl_xor_sync(0xffffffffu, send, 8);
                    }
        }
        // Round 2 (xor 4): b bit1 = jg bit2
        float v2[2][3][2];
        {
            const bool hi = (jg >> 2) & 1;
            #pragma unroll
            for (int i = 0; i < 2; i++)
                #pragma unroll
                for (int g = 0; g < 3; g++)
                    #pragma unroll
                    for (int b = 0; b < 2; b++) {
                        float a = v4[i][g][b];
                        float c = v4[i][g][b + 2];
                        float send = hi ? a : c;
                        float keep = hi ? c : a;
                        v2[i][g][b] = keep + __shfl_xor_sync(0xffffffffu, send, 4);
                    }
        }
        // Round 3 (xor 2): b bit0 = jg bit1
        float v1[2][3];
        {
            const bool hi = (jg >> 1) & 1;
            #pragma unroll
            for (int i = 0; i < 2; i++)
                #pragma unroll
                for (int g = 0; g < 3; g++) {
                    float a = v2[i][g][0];
                    float c = v2[i][g][1];
                    float send = hi ? a : c;
                    float keep = hi ? c : a;
                    v1[i][g] = keep + __shfl_xor_sync(0xffffffffu, send, 2);
                }
        }
        // Round 4 (xor 1): k = jg bit0
        float sv[3];
        {
            const bool hi = jg & 1;
            #pragma unroll
            for (int g = 0; g < 3; g++) {
                float a = v1[0][g];
                float c = v1[1][g];
                float send = hi ? a : c;
                float keep = hi ? c : a;
                sv[g] = keep + __shfl_xor_sync(0xffffffffu, send, 1);
            }
        }

        float r = sigm(xr + sv[0] + bhr);
        float z = sigm(xz + sv[1] + bhz);
        float n = tanhf(xn + r * (sv[2] + bhn));
        float hold = sH[bl * HPITCH + kg];
        float hnew = (1.f - z) * n + z * hold;

        __stcg(&hnext[(size_t)bgl * HDIM + kg], hnew);
        if (WRITE_SEQ)
            __stcg(&h_seq[((size_t)bgl * TDIM + t) * HDIM + kg], hnew);

        // prefetch next step's precomputed input gates (independent of barrier)
        if (t + 1 < TDIM) {
            const float* xt = xgb + (size_t)(t + 1) * G3;
            xr = __ldcg(xt);
            xz = __ldcg(xt + HDIM);
            xn = __ldcg(xt + 2 * HDIM);
        }

        // inter-block barrier within this b-group (32 blocks), release/acquire
        __syncthreads();
        if (tid == 0) {
            asm volatile("red.release.gpu.global.add.u32 [%0], %1;"
                         :: "l"(bar), "r"(1u) : "memory");
            const unsigned target = 32u * (unsigned)(t + 1);
            unsigned vv;
            do {
                asm volatile("ld.acquire.gpu.global.u32 %0, [%1];"
                             : "=r"(vv) : "l"(bar) : "memory");
            } while (vv < target);
        }
        __syncthreads();
    }
}

// ---------------------------------------------------------------------------
__global__ void init_kernel(float* h) {
    int i = blockIdx.x * blockDim.x + threadIdx.x;
    h[i] = 0.f;                       // zeros both ping-pong buffers (2*64*512)
    if (i < 128) ((unsigned*)g_bar)[i] = 0u;
}

__global__ void fc_kernel(const float* __restrict__ h, const float* __restrict__ W,
                          const float* __restrict__ bias, float* __restrict__ out)
{
    const int b = blockIdx.x;
    float s = 0.f;
    for (int k = threadIdx.x; k < HDIM; k += 128)
        s += h[(size_t)b * HDIM + k] * W[k];
    __shared__ float red[128];
    red[threadIdx.x] = s; __syncthreads();
    for (int off = 64; off > 0; off >>= 1) {
        if (threadIdx.x < off) red[threadIdx.x] += red[threadIdx.x + off];
        __syncthreads();
    }
    if (threadIdx.x == 0) out[b] = red[0] + bias[0];
}

// ---------------------------------------------------------------------------
extern "C" void kernel_launch(void* const* d_in, const int* in_sizes, int n_in,
                              void* d_out, int out_size)
{
    const float* X     = (const float*)d_in[0];
    const float* W_ih0 = (const float*)d_in[1];
    const float* W_hh0 = (const float*)d_in[2];
    const float* b_ih0 = (const float*)d_in[3];
    const float* b_hh0 = (const float*)d_in[4];
    const float* W_ih1 = (const float*)d_in[5];
    const float* W_hh1 = (const float*)d_in[6];
    const float* b_ih1 = (const float*)d_in[7];
    const float* b_hh1 = (const float*)d_in[8];
    const float* fc_W  = (const float*)d_in[9];
    const float* fc_b  = (const float*)d_in[10];
    float* out = (float*)d_out;

    float *xg, *hseq, *hbuf;
    cudaGetSymbolAddress((void**)&xg, g_xg);
    cudaGetSymbolAddress((void**)&hseq, g_hseq);
    cudaGetSymbolAddress((void**)&hbuf, g_h);

    cudaFuncSetAttribute(scan_kernel<true>,
                         cudaFuncAttributeMaxDynamicSharedMemorySize, SMEM_SCAN);
    cudaFuncSetAttribute(scan_kernel<false>,
                         cudaFuncAttributeMaxDynamicSharedMemorySize, SMEM_SCAN);
    cudaFuncSetAttribute(proj_kernel<INDIM>,
                         cudaFuncAttributeMaxDynamicSharedMemorySize, SMEM_PROJ);
    cudaFuncSetAttribute(proj_kernel<HDIM>,
                         cudaFuncAttributeMaxDynamicSharedMemorySize, SMEM_PROJ);

    const dim3 pgrid(BDIM * TDIM / 128, G3 / 64);
    const size_t HB = (size_t)BDIM * HDIM;

    // Layer 0
    proj_kernel<INDIM><<<pgrid, 256, SMEM_PROJ>>>(X, W_ih0, b_ih0, xg);
    init_kernel<<<128, 512>>>(hbuf);
    scan_kernel<true><<<dim3(32, 4), 256, SMEM_SCAN>>>(
        W_hh0, b_hh0, xg, hbuf, hbuf + HB, hseq);

    // Layer 1
    proj_kernel<HDIM><<<pgrid, 256, SMEM_PROJ>>>(hseq, W_ih1, b_ih1, xg);
    init_kernel<<<128, 512>>>(hbuf);
    scan_kernel<false><<<dim3(32, 4), 256, SMEM_SCAN>>>(
        W_hh1, b_hh1, xg, hbuf, hbuf + HB, nullptr);

    // Final h (after 512 steps) sits in parity-0 buffer
    fc_kernel<<<BDIM, 128>>>(hbuf, fc_W, fc_b, out);
}

// round 5
// speedup vs baseline: 1.4544x; 1.0475x over previous
#include <cuda_runtime.h>

#define BDIM 64
#define TDIM 512
#define INDIM 128
#define HDIM 512
#define G3 (3*HDIM)

#define WPITCH 520   // 16B-aligned rows
#define HPITCH 520
#define SMEM_SCAN ((48*WPITCH + 16*HPITCH)*4)   // 64*520*4 = 133120 B

#define PJP 34                                   // proj smem pitch (floats)
#define SMEM_PROJ ((2*128*PJP + 2*64*PJP)*4)     // 52224 B

// Static device scratch (no runtime allocation anywhere)
__device__ float g_xg[(size_t)BDIM * TDIM * G3];     // [B,T,3H] gate pre-activations
__device__ float g_hseq[(size_t)BDIM * TDIM * HDIM]; // layer-0 hidden sequence
__device__ float g_h[2][BDIM * HDIM];                // ping-pong hidden state
__device__ __align__(128) unsigned g_bar[4][32];     // one 128B line per b-group

typedef unsigned long long ull;

__device__ __forceinline__ void fma2(ull &d, ull a, ull b) {
    asm("fma.rn.f32x2 %0, %1, %2, %0;" : "+l"(d) : "l"(a), "l"(b));
}
__device__ __forceinline__ float ull_sum(ull a) {
    union { ull u; float2 f; } c; c.u = a; return c.f.x + c.f.y;
}
__device__ __forceinline__ float sigm(float x) { return 1.f / (1.f + __expf(-x)); }
__device__ __forceinline__ float tanh_fast(float x) {
    float e = __expf(2.f * x);
    return 1.f - 2.f / (e + 1.f);
}

__device__ __forceinline__ void cp8(float* s, const float* g) {
    unsigned ss = (unsigned)__cvta_generic_to_shared(s);
    asm volatile("cp.async.ca.shared.global [%0], [%1], 8;" :: "r"(ss), "l"(g));
}
__device__ __forceinline__ void cp_commit() {
    asm volatile("cp.async.commit_group;");
}

// ---------------------------------------------------------------------------
// Input projection GEMM: C[M,1536] = A[M,K] @ W[1536,K]^T + bias
// 128x64 tile, BK=32, 256 threads, 8x4 micro-tile, cp.async double buffering,
// 2 blocks/SM for latency hiding.
// ---------------------------------------------------------------------------
template<int K>
__global__ void __launch_bounds__(256, 2) proj_kernel(const float* __restrict__ A,
                                                      const float* __restrict__ W,
                                                      const float* __restrict__ bias,
                                                      float* __restrict__ C)
{
    extern __shared__ float ps[];
    float* AsBase = ps;                 // 2 x (128 x PJP)
    float* BsBase = ps + 2 * 128 * PJP; // 2 x (64 x PJP)
    const int m0 = blockIdx.x * 128;
    const int n0 = blockIdx.y * 64;
    const int tid = threadIdx.x;
    const int tx = tid & 15;   // N direction (4 cols each)
    const int ty = tid >> 4;   // M direction (8 rows each)
    const int NT = K / 32;

    ull acc[8][4];
    #pragma unroll
    for (int i = 0; i < 8; i++)
        #pragma unroll
        for (int j = 0; j < 4; j++) acc[i][j] = 0ull;

    auto stage = [&](int kt, int buf) {
        float* Ad = AsBase + buf * 128 * PJP;
        float* Bd = BsBase + buf * 64 * PJP;
        #pragma unroll
        for (int i = tid; i < 1024; i += 256) {
            int row = i >> 3, c4 = i & 7;
            const float* g = &A[(size_t)(m0 + row) * K + kt + c4 * 4];
            float* d = &Ad[row * PJP + c4 * 4];
            cp8(d, g); cp8(d + 2, g + 2);
        }
        #pragma unroll
        for (int i = tid; i < 512; i += 256) {
            int row = i >> 3, c4 = i & 7;
            const float* g = &W[(size_t)(n0 + row) * K + kt + c4 * 4];
            float* d = &Bd[row * PJP + c4 * 4];
            cp8(d, g); cp8(d + 2, g + 2);
        }
        cp_commit();
    };

    stage(0, 0);
    for (int kt = 0; kt < NT; kt++) {
        if (kt + 1 < NT) {
            stage((kt + 1) * 32, (kt + 1) & 1);
            asm volatile("cp.async.wait_group 1;");
        } else {
            asm volatile("cp.async.wait_group 0;");
        }
        __syncthreads();

        const float* As = AsBase + (kt & 1) * 128 * PJP;
        const float* Bs = BsBase + (kt & 1) * 64 * PJP;
        #pragma unroll
        for (int k2 = 0; k2 < 16; k2++) {
            ull a2[8], b2[4];
            #pragma unroll
            for (int i = 0; i < 8; i++)
                a2[i] = *(const ull*)&As[(ty * 8 + i) * PJP + k2 * 2];
            #pragma unroll
            for (int j = 0; j < 4; j++)
                b2[j] = *(const ull*)&Bs[(tx * 4 + j) * PJP + k2 * 2];
            #pragma unroll
            for (int i = 0; i < 8; i++)
                #pragma unroll
                for (int j = 0; j < 4; j++)
                    fma2(acc[i][j], a2[i], b2[j]);
        }
        __syncthreads();
    }

    #pragma unroll
    for (int i = 0; i < 8; i++) {
        int m = m0 + ty * 8 + i;
        #pragma unroll
        for (int j = 0; j < 4; j++) {
            int n = n0 + tx * 4 + j;
            C[(size_t)m * G3 + n] = ull_sum(acc[i][j]) + bias[n];
        }
    }
}

// ---------------------------------------------------------------------------
// Persistent GRU scan. Grid (32 k-tiles, 4 b-groups), 256 threads, all resident.
// W_hh staged in smem once. Per step: stage 16x512 h tile, micro-tile
// 2k x 3g x 8b x (16 lanes x 4-float j-chunks) per thread (LDS.128),
// tree-exchange shfl reduction, gate math (1 cell/lane),
// release/acquire inter-block barrier with work overlapped into the wait.
// ---------------------------------------------------------------------------
template<bool WRITE_SEQ>
__global__ void __launch_bounds__(256, 1) scan_kernel(
    const float* __restrict__ W_hh, const float* __restrict__ b_hh,
    const float* __restrict__ xg, float* __restrict__ h0buf,
    float* __restrict__ h1buf, float* __restrict__ h_seq)
{
    extern __shared__ float smem[];
    float* sW = smem;                 // 48 rows x 512 (pitch WPITCH)
    float* sH = smem + 48 * WPITCH;   // 16 rows x 512 (pitch HPITCH)

    const int tid = threadIdx.x;
    const int k0 = blockIdx.x * 16;
    const int b0 = blockIdx.y * 16;

    // Stage W_hh once (rows 0-15: r, 16-31: z, 32-47: n)
    for (int i = tid; i < 48 * 128; i += 256) {
        int row = i >> 7, c4 = i & 127;
        int g = row >> 4, r = row & 15;
        *(float4*)&sW[row * WPITCH + c4 * 4] =
            *(const float4*)&W_hh[(size_t)(g * HDIM + k0 + r) * HDIM + c4 * 4];
    }

    const int jg = tid & 15;         // j slice (4-float chunks)
    const int bg = (tid >> 4) & 1;   // batch half (8 rows)
    const int kk = tid >> 5;         // k pair (warp id)

    // epilogue cell owned by this lane (from the exchange tree)
    const int kl = kk * 2 + (jg & 1);
    const int bl = bg * 8 + ((jg >> 1) & 7);
    const int kg = k0 + kl;
    const int bgl = b0 + bl;

    const float bhr = b_hh[kg];
    const float bhz = b_hh[HDIM + kg];
    const float bhn = b_hh[2 * HDIM + kg];
    const float* xgb = xg + (size_t)bgl * TDIM * G3 + kg;

    const float4* wp[2][3];
    #pragma unroll
    for (int i = 0; i < 2; i++)
        #pragma unroll
        for (int g = 0; g < 3; g++)
            wp[i][g] = (const float4*)&sW[(g * 16 + kk * 2 + i) * WPITCH] + jg;
    const float4* hp[8];
    #pragma unroll
    for (int b = 0; b < 8; b++)
        hp[b] = (const float4*)&sH[(bg * 8 + b) * HPITCH] + jg;

    unsigned* bar = &g_bar[blockIdx.y][0];

    float xr = __ldcg(xgb);
    float xz = __ldcg(xgb + HDIM);
    float xn = __ldcg(xgb + 2 * HDIM);

    union F4 { float4 f; ull u[2]; };

    for (int t = 0; t < TDIM; t++) {
        const float* hprev = (t & 1) ? h1buf : h0buf;
        float* hnext = (t & 1) ? h0buf : h1buf;

        // stage h tile (pure float4 copy; HPITCH rows are 16B aligned)
        #pragma unroll
        for (int i = tid; i < 16 * 128; i += 256) {
            int row = i >> 7, c4 = i & 127;
            float4 v = __ldcg((const float4*)&hprev[(size_t)(b0 + row) * HDIM + c4 * 4]);
            *(float4*)&sH[row * HPITCH + c4 * 4] = v;
        }
        __syncthreads();

        ull acc[2][3][8];
        #pragma unroll
        for (int i = 0; i < 2; i++)
            #pragma unroll
            for (int g = 0; g < 3; g++)
                #pragma unroll
                for (int b = 0; b < 8; b++) acc[i][g][b] = 0ull;

        #pragma unroll 2
        for (int jc = 0; jc < 8; jc++) {
            const int off = jc * 16;   // float4 index stride per iter
            F4 h4[8];
            #pragma unroll
            for (int b = 0; b < 8; b++)
                h4[b].f = hp[b][off];
            #pragma unroll
            for (int i = 0; i < 2; i++)
                #pragma unroll
                for (int g = 0; g < 3; g++) {
                    F4 w4; w4.f = wp[i][g][off];
                    #pragma unroll
                    for (int b = 0; b < 8; b++) {
                        fma2(acc[i][g][b], h4[b].u[0], w4.u[0]);
                        fma2(acc[i][g][b], h4[b].u[1], w4.u[1]);
                    }
                }
        }

        // Tree-exchange reduction over the 16 j-slices
        float v4[2][3][4];
        {
            const bool hi = (jg >> 3) & 1;
            #pragma unroll
            for (int i = 0; i < 2; i++)
                #pragma unroll
                for (int g = 0; g < 3; g++)
                    #pragma unroll
                    for (int b = 0; b < 4; b++) {
                        float a = ull_sum(acc[i][g][b]);
                        float c = ull_sum(acc[i][g][b + 4]);
                        float send = hi ? a : c;
                        float keep = hi ? c : a;
                        v4[i][g][b] = keep + __shfl_xor_sync(0xffffffffu, send, 8);
                    }
        }
        float v2[2][3][2];
        {
            const bool hi = (jg >> 2) & 1;
            #pragma unroll
            for (int i = 0; i < 2; i++)
                #pragma unroll
                for (int g = 0; g < 3; g++)
                    #pragma unroll
                    for (int b = 0; b < 2; b++) {
                        float a = v4[i][g][b];
                        float c = v4[i][g][b + 2];
                        float send = hi ? a : c;
                        float keep = hi ? c : a;
                        v2[i][g][b] = keep + __shfl_xor_sync(0xffffffffu, send, 4);
                    }
        }
        float v1[2][3];
        {
            const bool hi = (jg >> 1) & 1;
            #pragma unroll
            for (int i = 0; i < 2; i++)
                #pragma unroll
                for (int g = 0; g < 3; g++) {
                    float a = v2[i][g][0];
                    float c = v2[i][g][1];
                    float send = hi ? a : c;
                    float keep = hi ? c : a;
                    v1[i][g] = keep + __shfl_xor_sync(0xffffffffu, send, 2);
                }
        }
        float sv[3];
        {
            const bool hi = jg & 1;
            #pragma unroll
            for (int g = 0; g < 3; g++) {
                float a = v1[0][g];
                float c = v1[1][g];
                float send = hi ? a : c;
                float keep = hi ? c : a;
                sv[g] = keep + __shfl_xor_sync(0xffffffffu, send, 1);
            }
        }

        float r = sigm(xr + sv[0] + bhr);
        float z = sigm(xz + sv[1] + bhz);
        float n = tanh_fast(xn + r * (sv[2] + bhn));
        float hold = sH[bl * HPITCH + kg];
        float hnew = (1.f - z) * n + z * hold;

        __stcg(&hnext[(size_t)bgl * HDIM + kg], hnew);

        // arrive as early as possible
        __syncthreads();
        if (tid == 0)
            asm volatile("red.release.gpu.global.add.u32 [%0], %1;"
                         :: "l"(bar), "r"(1u) : "memory");

        // overlap with barrier latency: h_seq store + next xg prefetch
        if (WRITE_SEQ)
            __stcg(&h_seq[((size_t)bgl * TDIM + t) * HDIM + kg], hnew);
        if (t + 1 < TDIM) {
            const float* xt = xgb + (size_t)(t + 1) * G3;
            xr = __ldcg(xt);
            xz = __ldcg(xt + HDIM);
            xn = __ldcg(xt + 2 * HDIM);
        }

        if (tid == 0) {
            const unsigned target = 32u * (unsigned)(t + 1);
            unsigned vv;
            do {
                asm volatile("ld.acquire.gpu.global.u32 %0, [%1];"
                             : "=r"(vv) : "l"(bar) : "memory");
            } while (vv < target);
        }
        __syncthreads();
    }
}

// ---------------------------------------------------------------------------
__global__ void init_kernel(float* h) {
    int i = blockIdx.x * blockDim.x + threadIdx.x;
    h[i] = 0.f;
    if (i < 128) ((unsigned*)g_bar)[i] = 0u;
}

__global__ void fc_kernel(const float* __restrict__ h, const float* __restrict__ W,
                          const float* __restrict__ bias, float* __restrict__ out)
{
    const int b = blockIdx.x;
    float s = 0.f;
    for (int k = threadIdx.x; k < HDIM; k += 128)
        s += h[(size_t)b * HDIM + k] * W[k];
    __shared__ float red[128];
    red[threadIdx.x] = s; __syncthreads();
    for (int off = 64; off > 0; off >>= 1) {
        if (threadIdx.x < off) red[threadIdx.x] += red[threadIdx.x + off];
        __syncthreads();
    }
    if (threadIdx.x == 0) out[b] = red[0] + bias[0];
}

// ---------------------------------------------------------------------------
extern "C" void kernel_launch(void* const* d_in, const int* in_sizes, int n_in,
                              void* d_out, int out_size)
{
    const float* X     = (const float*)d_in[0];
    const float* W_ih0 = (const float*)d_in[1];
    const float* W_hh0 = (const float*)d_in[2];
    const float* b_ih0 = (const float*)d_in[3];
    const float* b_hh0 = (const float*)d_in[4];
    const float* W_ih1 = (const float*)d_in[5];
    const float* W_hh1 = (const float*)d_in[6];
    const float* b_ih1 = (const float*)d_in[7];
    const float* b_hh1 = (const float*)d_in[8];
    const float* fc_W  = (const float*)d_in[9];
    const float* fc_b  = (const float*)d_in[10];
    float* out = (float*)d_out;

    float *xg, *hseq, *hbuf;
    cudaGetSymbolAddress((void**)&xg, g_xg);
    cudaGetSymbolAddress((void**)&hseq, g_hseq);
    cudaGetSymbolAddress((void**)&hbuf, g_h);

    cudaFuncSetAttribute(scan_kernel<true>,
                         cudaFuncAttributeMaxDynamicSharedMemorySize, SMEM_SCAN);
    cudaFuncSetAttribute(scan_kernel<false>,
                         cudaFuncAttributeMaxDynamicSharedMemorySize, SMEM_SCAN);
    cudaFuncSetAttribute(proj_kernel<INDIM>,
                         cudaFuncAttributeMaxDynamicSharedMemorySize, SMEM_PROJ);
    cudaFuncSetAttribute(proj_kernel<HDIM>,
                         cudaFuncAttributeMaxDynamicSharedMemorySize, SMEM_PROJ);

    const dim3 pgrid(BDIM * TDIM / 128, G3 / 64);
    const size_t HB = (size_t)BDIM * HDIM;

    // Layer 0
    proj_kernel<INDIM><<<pgrid, 256, SMEM_PROJ>>>(X, W_ih0, b_ih0, xg);
    init_kernel<<<128, 512>>>(hbuf);
    scan_kernel<true><<<dim3(32, 4), 256, SMEM_SCAN>>>(
        W_hh0, b_hh0, xg, hbuf, hbuf + HB, hseq);

    // Layer 1
    proj_kernel<HDIM><<<pgrid, 256, SMEM_PROJ>>>(hseq, W_ih1, b_ih1, xg);
    init_kernel<<<128, 512>>>(hbuf);
    scan_kernel<false><<<dim3(32, 4), 256, SMEM_SCAN>>>(
        W_hh1, b_hh1, xg, hbuf, hbuf + HB, nullptr);

    // Final h (after 512 steps) sits in parity-0 buffer
    fc_kernel<<<BDIM, 128>>>(hbuf, fc_W, fc_b, out);
}

// round 7
// speedup vs baseline: 1.7352x; 1.1931x over previous
#include <cuda_runtime.h>
#include <cuda_bf16.h>
#include <cstdint>

#define BDIM 64
#define TDIM 512
#define INDIM 128
#define HDIM 512
#define G3 (3*HDIM)

#define WPITCH 520
#define HPITCH 520
#define SMEM_SCAN ((48*WPITCH + 16*HPITCH)*4)   // 133120 B

// ---------------- static device scratch ----------------
__device__ float g_xg[(size_t)BDIM * TDIM * G3];
__device__ float g_hseq[(size_t)BDIM * TDIM * HDIM];
__device__ float g_h[2][BDIM * HDIM];
__device__ __align__(128) unsigned g_bar[4][32];
#define AMAX ((size_t)BDIM * TDIM * HDIM)
__device__ __nv_bfloat16 g_ahi[AMAX], g_alo[AMAX];
__device__ __nv_bfloat16 g_whi[G3 * HDIM], g_wlo[G3 * HDIM];

typedef unsigned long long ull;

__device__ __forceinline__ void fma2(ull &d, ull a, ull b) {
    asm("fma.rn.f32x2 %0, %1, %2, %0;" : "+l"(d) : "l"(a), "l"(b));
}
__device__ __forceinline__ float ull_sum(ull a) {
    union { ull u; float2 f; } c; c.u = a; return c.f.x + c.f.y;
}
__device__ __forceinline__ float sigm(float x) { return 1.f / (1.f + __expf(-x)); }
__device__ __forceinline__ float tanh_fast(float x) {
    float e = __expf(2.f * x);
    return 1.f - 2.f / (e + 1.f);
}
__device__ __forceinline__ uint32_t smem_u32(const void* p) {
    uint32_t a;
    asm("{ .reg .u64 t; cvta.to.shared.u64 t, %1; cvt.u32.u64 %0, t; }" : "=r"(a) : "l"(p));
    return a;
}
__device__ __forceinline__ void cp16(uint32_t saddr, const void* g) {
    asm volatile("cp.async.cg.shared.global [%0], [%1], 16;" :: "r"(saddr), "l"(g));
}
__device__ __forceinline__ void ldsm4(uint32_t& r0, uint32_t& r1, uint32_t& r2, uint32_t& r3,
                                      uint32_t addr) {
    asm volatile("ldmatrix.sync.aligned.m8n8.x4.shared.b16 {%0,%1,%2,%3}, [%4];"
                 : "=r"(r0), "=r"(r1), "=r"(r2), "=r"(r3) : "r"(addr));
}
__device__ __forceinline__ void mma16816(float* d, const uint32_t* a, const uint32_t* b) {
    asm volatile(
        "mma.sync.aligned.m16n8k16.row.col.f32.bf16.bf16.f32 "
        "{%0,%1,%2,%3}, {%4,%5,%6,%7}, {%8,%9}, {%0,%1,%2,%3};"
        : "+f"(d[0]), "+f"(d[1]), "+f"(d[2]), "+f"(d[3])
        : "r"(a[0]), "r"(a[1]), "r"(a[2]), "r"(a[3]), "r"(b[0]), "r"(b[1]));
}

// ============================================================================
// fp32 -> bf16 hi/lo split
// ============================================================================
__global__ void cvt_split(const float* __restrict__ x, __nv_bfloat16* __restrict__ hi,
                          __nv_bfloat16* __restrict__ lo, int n)
{
    int i = blockIdx.x * blockDim.x + threadIdx.x;
    if (i < n) {
        float v = x[i];
        __nv_bfloat16 h = __float2bfloat16(v);
        hi[i] = h;
        lo[i] = __float2bfloat16(v - __bfloat162float(h));
    }
}

// ============================================================================
// HMMA (mma.sync) bf16 split-precision GEMM:
//   C[M, G3] = A[M, K] @ W[G3, K]^T + bias   (fp32 accum)
//   D += Ahi*Whi + Ahi*Wlo + Alo*Whi
// Block 128x128, 8 warps (2x4), warp tile 64x32, K-chunks of 32,
// cp.async double buffering, ldmatrix fragments.
// ============================================================================
#define GP 40                      // smem pitch (bf16)
#define GTILE (128*GP)             // elems per tile
#define GTILE_B (GTILE*2)          // 10240 B
#define GBUF (4*GTILE)             // Ahi,Alo,Whi,Wlo
#define GBUF_B (4*GTILE_B)         // 40960 B
#define SMEM_GEMM (2*GBUF_B)       // 81920 B

template<int K>
__global__ void __launch_bounds__(256) gemm_kernel(
    const __nv_bfloat16* __restrict__ Ahi, const __nv_bfloat16* __restrict__ Alo,
    const __nv_bfloat16* __restrict__ Whi, const __nv_bfloat16* __restrict__ Wlo,
    const float* __restrict__ bias, float* __restrict__ C)
{
    extern __shared__ __nv_bfloat16 sm[];
    const uint32_t sbase = smem_u32(sm);
    const int tid = threadIdx.x;
    const int wid = tid >> 5;
    const int lane = tid & 31;
    const int m0 = blockIdx.x * 128;
    const int n0 = blockIdx.y * 128;
    constexpr int NC = K / 32;

    const __nv_bfloat16* srcs[4] = { Ahi + (size_t)m0 * K, Alo + (size_t)m0 * K,
                                     Whi + (size_t)n0 * K, Wlo + (size_t)n0 * K };

    // per-lane ldmatrix base addresses (byte offsets within a buffer)
    const int wm = (wid & 1) * 64;        // warp row offset
    const int wn = (wid >> 1) * 32;       // warp col offset
    // A: lanes 0-15 rows, lanes 16-31 same rows at k+8
    const uint32_t aOff = (uint32_t)((wm + (lane & 15)) * GP + (lane >> 4) * 8) * 2;
    // B (x4 = two n-tiles of 8): lanes>>4 selects n-tile, (lane>>3)&1 selects k half
    const uint32_t bOff = (uint32_t)((wn + (lane >> 4) * 8 + (lane & 7)) * GP
                                     + ((lane >> 3) & 1) * 8) * 2;

    float acc[4][4][4];
    #pragma unroll
    for (int mt = 0; mt < 4; mt++)
        #pragma unroll
        for (int nt = 0; nt < 4; nt++)
            #pragma unroll
            for (int q = 0; q < 4; q++) acc[mt][nt][q] = 0.f;

    auto stage = [&](int c, int p) {
        const uint32_t db = sbase + p * GBUF_B;
        #pragma unroll
        for (int t4 = 0; t4 < 4; t4++) {
            const __nv_bfloat16* s = srcs[t4] + c * 32;
            const uint32_t tb = db + t4 * GTILE_B;
            #pragma unroll
            for (int i = tid; i < 512; i += 256) {
                int r = i >> 2, ch = i & 3;
                cp16(tb + (uint32_t)(r * GP + ch * 8) * 2, s + (size_t)r * K + ch * 8);
            }
        }
        asm volatile("cp.async.commit_group;");
    };

    stage(0, 0);
    for (int c = 0; c < NC; c++) {
        const int p = c & 1;
        if (c + 1 < NC) {
            stage(c + 1, p ^ 1);
            asm volatile("cp.async.wait_group 1;");
        } else {
            asm volatile("cp.async.wait_group 0;");
        }
        __syncthreads();

        const uint32_t ab = sbase + p * GBUF_B + aOff;
        const uint32_t bb = sbase + p * GBUF_B + 2 * GTILE_B + bOff;

        #pragma unroll
        for (int k16 = 0; k16 < 2; k16++) {
            uint32_t Ah[4][4], Al[4][4], Bh[2][4], Bl[2][4];
            #pragma unroll
            for (int mt = 0; mt < 4; mt++) {
                const uint32_t a = ab + (uint32_t)(mt * 16 * GP + k16 * 16) * 2;
                ldsm4(Ah[mt][0], Ah[mt][1], Ah[mt][2], Ah[mt][3], a);
                ldsm4(Al[mt][0], Al[mt][1], Al[mt][2], Al[mt][3], a + GTILE_B);
            }
            #pragma unroll
            for (int np = 0; np < 2; np++) {
                const uint32_t b = bb + (uint32_t)(np * 16 * GP + k16 * 16) * 2;
                ldsm4(Bh[np][0], Bh[np][1], Bh[np][2], Bh[np][3], b);
                ldsm4(Bl[np][0], Bl[np][1], Bl[np][2], Bl[np][3], b + GTILE_B);
            }
            #pragma unroll
            for (int mt = 0; mt < 4; mt++)
                #pragma unroll
                for (int nt = 0; nt < 4; nt++) {
                    const uint32_t* bh = &Bh[nt >> 1][(nt & 1) * 2];
                    const uint32_t* bl = &Bl[nt >> 1][(nt & 1) * 2];
                    mma16816(acc[mt][nt], Ah[mt], bh);
                    mma16816(acc[mt][nt], Ah[mt], bl);
                    mma16816(acc[mt][nt], Al[mt], bh);
                }
        }
        __syncthreads();
    }

    // epilogue: registers -> C (+bias)
    const int mrow = m0 + wm + (lane >> 2);
    const int ncol = n0 + wn + (lane & 3) * 2;
    #pragma unroll
    for (int nt = 0; nt < 4; nt++) {
        const int n = ncol + nt * 8;
        const float b0 = __ldg(bias + n);
        const float b1 = __ldg(bias + n + 1);
        #pragma unroll
        for (int mt = 0; mt < 4; mt++) {
            const int m = mrow + mt * 16;
            float2 o0 = make_float2(acc[mt][nt][0] + b0, acc[mt][nt][1] + b1);
            float2 o1 = make_float2(acc[mt][nt][2] + b0, acc[mt][nt][3] + b1);
            *(float2*)&C[(size_t)m * G3 + n] = o0;
            *(float2*)&C[(size_t)(m + 8) * G3 + n] = o1;
        }
    }
}

// ============================================================================
// Persistent GRU scan (unchanged)
// ============================================================================
template<bool WRITE_SEQ>
__global__ void __launch_bounds__(256, 1) scan_kernel(
    const float* __restrict__ W_hh, const float* __restrict__ b_hh,
    const float* __restrict__ xg, float* __restrict__ h0buf,
    float* __restrict__ h1buf, float* __restrict__ h_seq)
{
    extern __shared__ float smemf[];
    float* sW = smemf;
    float* sH = smemf + 48 * WPITCH;

    const int tid = threadIdx.x;
    const int k0 = blockIdx.x * 16;
    const int b0 = blockIdx.y * 16;

    for (int i = tid; i < 48 * 128; i += 256) {
        int row = i >> 7, c4 = i & 127;
        int g = row >> 4, r = row & 15;
        *(float4*)&sW[row * WPITCH + c4 * 4] =
            *(const float4*)&W_hh[(size_t)(g * HDIM + k0 + r) * HDIM + c4 * 4];
    }

    const int jg = tid & 15;
    const int bg = (tid >> 4) & 1;
    const int kk = tid >> 5;

    const int kl = kk * 2 + (jg & 1);
    const int bl = bg * 8 + ((jg >> 1) & 7);
    const int kg = k0 + kl;
    const int bgl = b0 + bl;

    const float bhr = b_hh[kg];
    const float bhz = b_hh[HDIM + kg];
    const float bhn = b_hh[2 * HDIM + kg];
    const float* xgb = xg + (size_t)bgl * TDIM * G3 + kg;

    const float4* wp[2][3];
    #pragma unroll
    for (int i = 0; i < 2; i++)
        #pragma unroll
        for (int g = 0; g < 3; g++)
            wp[i][g] = (const float4*)&sW[(g * 16 + kk * 2 + i) * WPITCH] + jg;
    const float4* hp[8];
    #pragma unroll
    for (int b = 0; b < 8; b++)
        hp[b] = (const float4*)&sH[(bg * 8 + b) * HPITCH] + jg;

    unsigned* bar = &g_bar[blockIdx.y][0];

    float xr = __ldcg(xgb);
    float xz = __ldcg(xgb + HDIM);
    float xn = __ldcg(xgb + 2 * HDIM);

    union F4 { float4 f; ull u[2]; };

    for (int t = 0; t < TDIM; t++) {
        const float* hprev = (t & 1) ? h1buf : h0buf;
        float* hnext = (t & 1) ? h0buf : h1buf;

        #pragma unroll
        for (int i = tid; i < 16 * 128; i += 256) {
            int row = i >> 7, c4 = i & 127;
            float4 v = __ldcg((const float4*)&hprev[(size_t)(b0 + row) * HDIM + c4 * 4]);
            *(float4*)&sH[row * HPITCH + c4 * 4] = v;
        }
        __syncthreads();

        ull acc[2][3][8];
        #pragma unroll
        for (int i = 0; i < 2; i++)
            #pragma unroll
            for (int g = 0; g < 3; g++)
                #pragma unroll
                for (int b = 0; b < 8; b++) acc[i][g][b] = 0ull;

        #pragma unroll 2
        for (int jc = 0; jc < 8; jc++) {
            const int off = jc * 16;
            F4 h4[8];
            #pragma unroll
            for (int b = 0; b < 8; b++)
                h4[b].f = hp[b][off];
            #pragma unroll
            for (int i = 0; i < 2; i++)
                #pragma unroll
                for (int g = 0; g < 3; g++) {
                    F4 w4; w4.f = wp[i][g][off];
                    #pragma unroll
                    for (int b = 0; b < 8; b++) {
                        fma2(acc[i][g][b], h4[b].u[0], w4.u[0]);
                        fma2(acc[i][g][b], h4[b].u[1], w4.u[1]);
                    }
                }
        }

        float v4[2][3][4];
        {
            const bool hi = (jg >> 3) & 1;
            #pragma unroll
            for (int i = 0; i < 2; i++)
                #pragma unroll
                for (int g = 0; g < 3; g++)
                    #pragma unroll
                    for (int b = 0; b < 4; b++) {
                        float a = ull_sum(acc[i][g][b]);
                        float c = ull_sum(acc[i][g][b + 4]);
                        float send = hi ? a : c;
                        float keep = hi ? c : a;
                        v4[i][g][b] = keep + __shfl_xor_sync(0xffffffffu, send, 8);
                    }
        }
        float v2[2][3][2];
        {
            const bool hi = (jg >> 2) & 1;
            #pragma unroll
            for (int i = 0; i < 2; i++)
                #pragma unroll
                for (int g = 0; g < 3; g++)
                    #pragma unroll
                    for (int b = 0; b < 2; b++) {
                        float a = v4[i][g][b];
                        float c = v4[i][g][b + 2];
                        float send = hi ? a : c;
                        float keep = hi ? c : a;
                        v2[i][g][b] = keep + __shfl_xor_sync(0xffffffffu, send, 4);
                    }
        }
        float v1[2][3];
        {
            const bool hi = (jg >> 1) & 1;
            #pragma unroll
            for (int i = 0; i < 2; i++)
                #pragma unroll
                for (int g = 0; g < 3; g++) {
                    float a = v2[i][g][0];
                    float c = v2[i][g][1];
                    float send = hi ? a : c;
                    float keep = hi ? c : a;
                    v1[i][g] = keep + __shfl_xor_sync(0xffffffffu, send, 2);
                }
        }
        float sv[3];
        {
            const bool hi = jg & 1;
            #pragma unroll
            for (int g = 0; g < 3; g++) {
                float a = v1[0][g];
                float c = v1[1][g];
                float send = hi ? a : c;
                float keep = hi ? c : a;
                sv[g] = keep + __shfl_xor_sync(0xffffffffu, send, 1);
            }
        }

        float r = sigm(xr + sv[0] + bhr);
        float z = sigm(xz + sv[1] + bhz);
        float n = tanh_fast(xn + r * (sv[2] + bhn));
        float hold = sH[bl * HPITCH + kg];
        float hnew = (1.f - z) * n + z * hold;

        __stcg(&hnext[(size_t)bgl * HDIM + kg], hnew);

        __syncthreads();
        if (tid == 0)
            asm volatile("red.release.gpu.global.add.u32 [%0], %1;"
                         :: "l"(bar), "r"(1u) : "memory");

        if (WRITE_SEQ)
            __stcg(&h_seq[((size_t)bgl * TDIM + t) * HDIM + kg], hnew);
        if (t + 1 < TDIM) {
            const float* xt = xgb + (size_t)(t + 1) * G3;
            xr = __ldcg(xt);
            xz = __ldcg(xt + HDIM);
            xn = __ldcg(xt + 2 * HDIM);
        }

        if (tid == 0) {
            const unsigned target = 32u * (unsigned)(t + 1);
            unsigned vv;
            do {
                asm volatile("ld.acquire.gpu.global.u32 %0, [%1];"
                             : "=r"(vv) : "l"(bar) : "memory");
            } while (vv < target);
        }
        __syncthreads();
    }
}

// ---------------------------------------------------------------------------
__global__ void init_kernel(float* h) {
    int i = blockIdx.x * blockDim.x + threadIdx.x;
    h[i] = 0.f;
    if (i < 128) ((unsigned*)g_bar)[i] = 0u;
}

__global__ void fc_kernel(const float* __restrict__ h, const float* __restrict__ W,
                          const float* __restrict__ bias, float* __restrict__ out)
{
    const int b = blockIdx.x;
    float s = 0.f;
    for (int k = threadIdx.x; k < HDIM; k += 128)
        s += h[(size_t)b * HDIM + k] * W[k];
    __shared__ float red[128];
    red[threadIdx.x] = s; __syncthreads();
    for (int off = 64; off > 0; off >>= 1) {
        if (threadIdx.x < off) red[threadIdx.x] += red[threadIdx.x + off];
        __syncthreads();
    }
    if (threadIdx.x == 0) out[b] = red[0] + bias[0];
}

// ---------------------------------------------------------------------------
extern "C" void kernel_launch(void* const* d_in, const int* in_sizes, int n_in,
                              void* d_out, int out_size)
{
    const float* X     = (const float*)d_in[0];
    const float* W_ih0 = (const float*)d_in[1];
    const float* W_hh0 = (const float*)d_in[2];
    const float* b_ih0 = (const float*)d_in[3];
    const float* b_hh0 = (const float*)d_in[4];
    const float* W_ih1 = (const float*)d_in[5];
    const float* W_hh1 = (const float*)d_in[6];
    const float* b_ih1 = (const float*)d_in[7];
    const float* b_hh1 = (const float*)d_in[8];
    const float* fc_W  = (const float*)d_in[9];
    const float* fc_b  = (const float*)d_in[10];
    float* out = (float*)d_out;

    float *xg, *hseq, *hbuf;
    __nv_bfloat16 *ahi, *alo, *whi, *wlo;
    cudaGetSymbolAddress((void**)&xg, g_xg);
    cudaGetSymbolAddress((void**)&hseq, g_hseq);
    cudaGetSymbolAddress((void**)&hbuf, g_h);
    cudaGetSymbolAddress((void**)&ahi, g_ahi);
    cudaGetSymbolAddress((void**)&alo, g_alo);
    cudaGetSymbolAddress((void**)&whi, g_whi);
    cudaGetSymbolAddress((void**)&wlo, g_wlo);

    cudaFuncSetAttribute(scan_kernel<true>,
                         cudaFuncAttributeMaxDynamicSharedMemorySize, SMEM_SCAN);
    cudaFuncSetAttribute(scan_kernel<false>,
                         cudaFuncAttributeMaxDynamicSharedMemorySize, SMEM_SCAN);
    cudaFuncSetAttribute(gemm_kernel<INDIM>,
                         cudaFuncAttributeMaxDynamicSharedMemorySize, SMEM_GEMM);
    cudaFuncSetAttribute(gemm_kernel<HDIM>,
                         cudaFuncAttributeMaxDynamicSharedMemorySize, SMEM_GEMM);

    const size_t HB = (size_t)BDIM * HDIM;
    const int M = BDIM * TDIM;                 // 32768
    const dim3 ggrid(M / 128, G3 / 128);       // (256, 12)

    // ---- Layer 0 ----
    cvt_split<<<(M * INDIM + 255) / 256, 256>>>(X, ahi, alo, M * INDIM);
    cvt_split<<<(G3 * INDIM + 255) / 256, 256>>>(W_ih0, whi, wlo, G3 * INDIM);
    gemm_kernel<INDIM><<<ggrid, 256, SMEM_GEMM>>>(ahi, alo, whi, wlo, b_ih0, xg);
    init_kernel<<<128, 512>>>(hbuf);
    scan_kernel<true><<<dim3(32, 4), 256, SMEM_SCAN>>>(
        W_hh0, b_hh0, xg, hbuf, hbuf + HB, hseq);

    // ---- Layer 1 ----
    cvt_split<<<(M * HDIM + 255) / 256, 256>>>(hseq, ahi, alo, M * HDIM);
    cvt_split<<<(G3 * HDIM + 255) / 256, 256>>>(W_ih1, whi, wlo, G3 * HDIM);
    gemm_kernel<HDIM><<<ggrid, 256, SMEM_GEMM>>>(ahi, alo, whi, wlo, b_ih1, xg);
    init_kernel<<<128, 512>>>(hbuf);
    scan_kernel<false><<<dim3(32, 4), 256, SMEM_SCAN>>>(
        W_hh1, b_hh1, xg, hbuf, hbuf + HB, nullptr);

    fc_kernel<<<BDIM, 128>>>(hbuf, fc_W, fc_b, out);
}

// round 8
// speedup vs baseline: 2.4211x; 1.3952x over previous
#include <cuda_runtime.h>
#include <cuda_bf16.h>
#include <cstdint>

#define BDIM 64
#define TDIM 512
#define INDIM 128
#define HDIM 512
#define G3 (3*HDIM)

// ---------------- static device scratch ----------------
__device__ float g_xg[(size_t)BDIM * TDIM * G3];
__device__ float g_hseq[(size_t)BDIM * TDIM * HDIM];
__device__ float g_h[2][BDIM * HDIM];
__device__ __align__(128) unsigned g_bar[4][32];
#define AMAX ((size_t)BDIM * TDIM * HDIM)
__device__ __nv_bfloat16 g_ahi[AMAX], g_alo[AMAX];
__device__ __nv_bfloat16 g_whi[G3 * HDIM], g_wlo[G3 * HDIM];

typedef unsigned long long ull;

__device__ __forceinline__ void fma2(ull &d, ull a, ull b) {
    asm("fma.rn.f32x2 %0, %1, %2, %0;" : "+l"(d) : "l"(a), "l"(b));
}
__device__ __forceinline__ float ull_sum(ull a) {
    union { ull u; float2 f; } c; c.u = a; return c.f.x + c.f.y;
}
__device__ __forceinline__ float sigm(float x) { return 1.f / (1.f + __expf(-x)); }
__device__ __forceinline__ float tanh_fast(float x) {
    float e = __expf(2.f * x);
    return 1.f - 2.f / (e + 1.f);
}
__device__ __forceinline__ uint32_t smem_u32(const void* p) {
    uint32_t a;
    asm("{ .reg .u64 t; cvta.to.shared.u64 t, %1; cvt.u32.u64 %0, t; }" : "=r"(a) : "l"(p));
    return a;
}
__device__ __forceinline__ void cp16(uint32_t saddr, const void* g) {
    asm volatile("cp.async.cg.shared.global [%0], [%1], 16;" :: "r"(saddr), "l"(g));
}
__device__ __forceinline__ void ldsm4(uint32_t& r0, uint32_t& r1, uint32_t& r2, uint32_t& r3,
                                      uint32_t addr) {
    asm volatile("ldmatrix.sync.aligned.m8n8.x4.shared.b16 {%0,%1,%2,%3}, [%4];"
                 : "=r"(r0), "=r"(r1), "=r"(r2), "=r"(r3) : "r"(addr));
}
__device__ __forceinline__ void mma16816(float* d, const uint32_t* a, const uint32_t* b) {
    asm volatile(
        "mma.sync.aligned.m16n8k16.row.col.f32.bf16.bf16.f32 "
        "{%0,%1,%2,%3}, {%4,%5,%6,%7}, {%8,%9}, {%0,%1,%2,%3};"
        : "+f"(d[0]), "+f"(d[1]), "+f"(d[2]), "+f"(d[3])
        : "r"(a[0]), "r"(a[1]), "r"(a[2]), "r"(a[3]), "r"(b[0]), "r"(b[1]));
}

// fp32x4 -> packed bf16 hi (uint2 = 4 bf16) + lo
__device__ __forceinline__ void cvt_pair(float4 v, uint2& hi, uint2& lo) {
    __nv_bfloat162 h0 = __floats2bfloat162_rn(v.x, v.y);
    __nv_bfloat162 h1 = __floats2bfloat162_rn(v.z, v.w);
    float2 f0 = __bfloat1622float2(h0);
    float2 f1 = __bfloat1622float2(h1);
    __nv_bfloat162 l0 = __floats2bfloat162_rn(v.x - f0.x, v.y - f0.y);
    __nv_bfloat162 l1 = __floats2bfloat162_rn(v.z - f1.x, v.w - f1.y);
    hi.x = *reinterpret_cast<unsigned*>(&h0);
    hi.y = *reinterpret_cast<unsigned*>(&h1);
    lo.x = *reinterpret_cast<unsigned*>(&l0);
    lo.y = *reinterpret_cast<unsigned*>(&l1);
}

// ============================================================================
// fp32 -> bf16 hi/lo split (for projection GEMM operands)
// ============================================================================
__global__ void cvt_split(const float* __restrict__ x, __nv_bfloat16* __restrict__ hi,
                          __nv_bfloat16* __restrict__ lo, int n)
{
    int i = blockIdx.x * blockDim.x + threadIdx.x;
    if (i < n) {
        float v = x[i];
        __nv_bfloat16 h = __float2bfloat16(v);
        hi[i] = h;
        lo[i] = __float2bfloat16(v - __bfloat162float(h));
    }
}

// ============================================================================
// HMMA (mma.sync) bf16 split-precision projection GEMM (unchanged, R7-passing)
// ============================================================================
#define GP 40
#define GTILE (128*GP)
#define GTILE_B (GTILE*2)
#define GBUF_B (4*GTILE_B)
#define SMEM_GEMM (2*GBUF_B)

template<int K>
__global__ void __launch_bounds__(256) gemm_kernel(
    const __nv_bfloat16* __restrict__ Ahi, const __nv_bfloat16* __restrict__ Alo,
    const __nv_bfloat16* __restrict__ Whi, const __nv_bfloat16* __restrict__ Wlo,
    const float* __restrict__ bias, float* __restrict__ C)
{
    extern __shared__ __nv_bfloat16 smg[];
    const uint32_t sbase = smem_u32(smg);
    const int tid = threadIdx.x;
    const int wid = tid >> 5;
    const int lane = tid & 31;
    const int m0 = blockIdx.x * 128;
    const int n0 = blockIdx.y * 128;
    constexpr int NC = K / 32;

    const __nv_bfloat16* srcs[4] = { Ahi + (size_t)m0 * K, Alo + (size_t)m0 * K,
                                     Whi + (size_t)n0 * K, Wlo + (size_t)n0 * K };

    const int wm = (wid & 1) * 64;
    const int wn = (wid >> 1) * 32;
    const uint32_t aOff = (uint32_t)((wm + (lane & 15)) * GP + (lane >> 4) * 8) * 2;
    const uint32_t bOff = (uint32_t)((wn + (lane >> 4) * 8 + (lane & 7)) * GP
                                     + ((lane >> 3) & 1) * 8) * 2;

    float acc[4][4][4];
    #pragma unroll
    for (int mt = 0; mt < 4; mt++)
        #pragma unroll
        for (int nt = 0; nt < 4; nt++)
            #pragma unroll
            for (int q = 0; q < 4; q++) acc[mt][nt][q] = 0.f;

    auto stage = [&](int c, int p) {
        const uint32_t db = sbase + p * GBUF_B;
        #pragma unroll
        for (int t4 = 0; t4 < 4; t4++) {
            const __nv_bfloat16* s = srcs[t4] + c * 32;
            const uint32_t tb = db + t4 * GTILE_B;
            #pragma unroll
            for (int i = tid; i < 512; i += 256) {
                int r = i >> 2, ch = i & 3;
                cp16(tb + (uint32_t)(r * GP + ch * 8) * 2, s + (size_t)r * K + ch * 8);
            }
        }
        asm volatile("cp.async.commit_group;");
    };

    stage(0, 0);
    for (int c = 0; c < NC; c++) {
        const int p = c & 1;
        if (c + 1 < NC) {
            stage(c + 1, p ^ 1);
            asm volatile("cp.async.wait_group 1;");
        } else {
            asm volatile("cp.async.wait_group 0;");
        }
        __syncthreads();

        const uint32_t ab = sbase + p * GBUF_B + aOff;
        const uint32_t bb = sbase + p * GBUF_B + 2 * GTILE_B + bOff;

        #pragma unroll
        for (int k16 = 0; k16 < 2; k16++) {
            uint32_t Ah[4][4], Al[4][4], Bh[2][4], Bl[2][4];
            #pragma unroll
            for (int mt = 0; mt < 4; mt++) {
                const uint32_t a = ab + (uint32_t)(mt * 16 * GP + k16 * 16) * 2;
                ldsm4(Ah[mt][0], Ah[mt][1], Ah[mt][2], Ah[mt][3], a);
                ldsm4(Al[mt][0], Al[mt][1], Al[mt][2], Al[mt][3], a + GTILE_B);
            }
            #pragma unroll
            for (int np = 0; np < 2; np++) {
                const uint32_t b = bb + (uint32_t)(np * 16 * GP + k16 * 16) * 2;
                ldsm4(Bh[np][0], Bh[np][1], Bh[np][2], Bh[np][3], b);
                ldsm4(Bl[np][0], Bl[np][1], Bl[np][2], Bl[np][3], b + GTILE_B);
            }
            #pragma unroll
            for (int mt = 0; mt < 4; mt++)
                #pragma unroll
                for (int nt = 0; nt < 4; nt++) {
                    const uint32_t* bh = &Bh[nt >> 1][(nt & 1) * 2];
                    const uint32_t* bl = &Bl[nt >> 1][(nt & 1) * 2];
                    mma16816(acc[mt][nt], Ah[mt], bh);
                    mma16816(acc[mt][nt], Ah[mt], bl);
                    mma16816(acc[mt][nt], Al[mt], bh);
                }
        }
        __syncthreads();
    }

    const int mrow = m0 + wm + (lane >> 2);
    const int ncol = n0 + wn + (lane & 3) * 2;
    #pragma unroll
    for (int nt = 0; nt < 4; nt++) {
        const int n = ncol + nt * 8;
        const float b0 = __ldg(bias + n);
        const float b1 = __ldg(bias + n + 1);
        #pragma unroll
        for (int mt = 0; mt < 4; mt++) {
            const int m = mrow + mt * 16;
            float2 o0 = make_float2(acc[mt][nt][0] + b0, acc[mt][nt][1] + b1);
            float2 o1 = make_float2(acc[mt][nt][2] + b0, acc[mt][nt][3] + b1);
            *(float2*)&C[(size_t)m * G3 + n] = o0;
            *(float2*)&C[(size_t)(m + 8) * G3 + n] = o1;
        }
    }
}

// ============================================================================
// Persistent HMMA GRU scan.
// Grid (32 k-tiles, 4 b-groups), 256 threads, 128 resident blocks.
// W_hh (48 rows x 512) staged ONCE as bf16 hi/lo (ldmatrix layout).
// Per step: stage h (fp32 -> bf16 hi/lo), warp w does K-slice [64w,64w+64):
//   72 m16n8k16 MMAs (Ahi*Bhi + Ahi*Blo + Alo*Bhi), fp32 acc (M16 x N48).
// Accs -> smem, cross-warp reduce (8), gate math (1 cell/thread), store,
// release/acquire inter-block barrier per b-group.
// ============================================================================
#define HP 520                     // bf16 pitch
#define OFF_WHI 0
#define OFF_WLO 49920              // 48*520*2
#define OFF_HHI 99840
#define OFF_HLO 116480             // +16*520*2
#define OFF_R   133120
#define SRP 800                    // reduce-buffer pitch (floats) per warp
#define SMEM_SCAN (OFF_R + 8*SRP*4)   // 158720 B

template<bool WRITE_SEQ>
__global__ void __launch_bounds__(256, 1) scan_kernel(
    const float* __restrict__ W_hh, const float* __restrict__ b_hh,
    const float* __restrict__ xg, float* __restrict__ h0buf,
    float* __restrict__ h1buf, float* __restrict__ h_seq)
{
    extern __shared__ char sms[];
    const uint32_t sb = smem_u32(sms);
    float* sR = (float*)(sms + OFF_R);

    const int tid = threadIdx.x;
    const int wid = tid >> 5;
    const int lane = tid & 31;
    const int k0 = blockIdx.x * 16;
    const int b0 = blockIdx.y * 16;

    // ---- stage W_hh once: rows n = g*16 + k (48 rows x 512), bf16 hi/lo ----
    for (int i = tid; i < 48 * 128; i += 256) {
        int r = i >> 7, c4 = i & 127;
        int g = r >> 4, kr = r & 15;
        float4 v = *(const float4*)&W_hh[(size_t)(g * HDIM + k0 + kr) * HDIM + c4 * 4];
        uint2 hi, lo; cvt_pair(v, hi, lo);
        *(uint2*)(sms + OFF_WHI + (r * HP + c4 * 4) * 2) = hi;
        *(uint2*)(sms + OFF_WLO + (r * HP + c4 * 4) * 2) = lo;
    }

    // ---- per-warp ldmatrix base addresses ----
    const int jb = wid * 64;  // K-slice base (bf16 cols)
    const uint32_t aHi = sb + OFF_HHI + (uint32_t)((lane & 15) * HP + jb + (lane >> 4) * 8) * 2;
    const uint32_t aLo = aHi + (OFF_HLO - OFF_HHI);
    uint32_t bHi[3];
    #pragma unroll
    for (int ng = 0; ng < 3; ng++)
        bHi[ng] = sb + OFF_WHI + (uint32_t)((ng * 16 + (lane >> 4) * 8 + (lane & 7)) * HP
                                            + jb + ((lane >> 3) & 1) * 8) * 2;

    // ---- epilogue cell owned by this thread ----
    const int m = tid >> 4;          // batch row 0..15
    const int kq = tid & 15;         // k col 0..15
    const int bgl = b0 + m;
    const int kg = k0 + kq;
    const float bhr = b_hh[kg];
    const float bhz = b_hh[HDIM + kg];
    const float bhn = b_hh[2 * HDIM + kg];
    const float* xgb = xg + (size_t)bgl * TDIM * G3 + kg;

    unsigned* bar = &g_bar[blockIdx.y][0];

    for (int t = 0; t < TDIM; t++) {
        const float* hprev = (t & 1) ? h1buf : h0buf;
        float* hnext = (t & 1) ? h0buf : h1buf;

        // barrier: h(t) fully published when bar >= 32*t
        if (tid == 0) {
            const unsigned target = 32u * (unsigned)t;
            unsigned vv;
            do {
                asm volatile("ld.acquire.gpu.global.u32 %0, [%1];"
                             : "=r"(vv) : "l"(bar) : "memory");
            } while (vv < target);
        }
        __syncthreads();

        // stage h tile: 16 rows x 512, fp32 -> bf16 hi/lo
        #pragma unroll
        for (int i = tid; i < 16 * 128; i += 256) {
            int r = i >> 7, c4 = i & 127;
            float4 v = __ldcg((const float4*)&hprev[(size_t)(b0 + r) * HDIM + c4 * 4]);
            uint2 hi, lo; cvt_pair(v, hi, lo);
            *(uint2*)(sms + OFF_HHI + (r * HP + c4 * 4) * 2) = hi;
            *(uint2*)(sms + OFF_HLO + (r * HP + c4 * 4) * 2) = lo;
        }
        // prefetch this cell's input gates (independent)
        const float* xt = xgb + (size_t)t * G3;
        float xr = __ldcg(xt);
        float xz = __ldcg(xt + HDIM);
        float xn = __ldcg(xt + 2 * HDIM);
        __syncthreads();

        // ---- MMA: warp's K-slice of 64, acc = M16 x N48 ----
        float acc[6][4];
        #pragma unroll
        for (int nt = 0; nt < 6; nt++)
            #pragma unroll
            for (int q = 0; q < 4; q++) acc[nt][q] = 0.f;

        #pragma unroll
        for (int k16 = 0; k16 < 4; k16++) {
            const uint32_t ko = k16 * 32;   // 16 bf16 = 32 B
            uint32_t Ah[4], Al[4];
            ldsm4(Ah[0], Ah[1], Ah[2], Ah[3], aHi + ko);
            ldsm4(Al[0], Al[1], Al[2], Al[3], aLo + ko);
            #pragma unroll
            for (int ng = 0; ng < 3; ng++) {
                uint32_t Bh[4], Bl[4];
                ldsm4(Bh[0], Bh[1], Bh[2], Bh[3], bHi[ng] + ko);
                ldsm4(Bl[0], Bl[1], Bl[2], Bl[3], bHi[ng] + (OFF_WLO - OFF_WHI) + ko);
                #pragma unroll
                for (int s = 0; s < 2; s++) {
                    float* d = acc[2 * ng + s];
                    mma16816(d, Ah, &Bh[s * 2]);
                    mma16816(d, Ah, &Bl[s * 2]);
                    mma16816(d, Al, &Bh[s * 2]);
                }
            }
        }

        // ---- dump accs to smem: sR[wid][mrow*50 + n] ----
        {
            float* out = sR + wid * SRP + (lane >> 2) * 50 + (lane & 3) * 2;
            #pragma unroll
            for (int nt = 0; nt < 6; nt++) {
                *(float2*)&out[nt * 8] = make_float2(acc[nt][0], acc[nt][1]);
                *(float2*)&out[400 + nt * 8] = make_float2(acc[nt][2], acc[nt][3]);
            }
        }
        __syncthreads();

        // ---- cross-warp reduce + gates (thread owns cell (m, kq)) ----
        float sr = 0.f, sz = 0.f, sn = 0.f;
        #pragma unroll
        for (int w = 0; w < 8; w++) {
            const float* rr = sR + w * SRP + m * 50;
            sr += rr[kq];
            sz += rr[16 + kq];
            sn += rr[32 + kq];
        }

        float r = sigm(xr + sr + bhr);
        float z = sigm(xz + sz + bhz);
        float n = tanh_fast(xn + r * (sn + bhn));
        float hold = __ldcg(&hprev[(size_t)bgl * HDIM + kg]);
        float hnew = (1.f - z) * n + z * hold;

        __stcg(&hnext[(size_t)bgl * HDIM + kg], hnew);
        if (WRITE_SEQ)
            __stcg(&h_seq[((size_t)bgl * TDIM + t) * HDIM + kg], hnew);

        __syncthreads();
        if (tid == 0)
            asm volatile("red.release.gpu.global.add.u32 [%0], %1;"
                         :: "l"(bar), "r"(1u) : "memory");
    }
}

// ---------------------------------------------------------------------------
__global__ void init_kernel(float* h) {
    int i = blockIdx.x * blockDim.x + threadIdx.x;
    h[i] = 0.f;
    if (i < 128) ((unsigned*)g_bar)[i] = 0u;
}

__global__ void fc_kernel(const float* __restrict__ h, const float* __restrict__ W,
                          const float* __restrict__ bias, float* __restrict__ out)
{
    const int b = blockIdx.x;
    float s = 0.f;
    for (int k = threadIdx.x; k < HDIM; k += 128)
        s += h[(size_t)b * HDIM + k] * W[k];
    __shared__ float red[128];
    red[threadIdx.x] = s; __syncthreads();
    for (int off = 64; off > 0; off >>= 1) {
        if (threadIdx.x < off) red[threadIdx.x] += red[threadIdx.x + off];
        __syncthreads();
    }
    if (threadIdx.x == 0) out[b] = red[0] + bias[0];
}

// ---------------------------------------------------------------------------
extern "C" void kernel_launch(void* const* d_in, const int* in_sizes, int n_in,
                              void* d_out, int out_size)
{
    const float* X     = (const float*)d_in[0];
    const float* W_ih0 = (const float*)d_in[1];
    const float* W_hh0 = (const float*)d_in[2];
    const float* b_ih0 = (const float*)d_in[3];
    const float* b_hh0 = (const float*)d_in[4];
    const float* W_ih1 = (const float*)d_in[5];
    const float* W_hh1 = (const float*)d_in[6];
    const float* b_ih1 = (const float*)d_in[7];
    const float* b_hh1 = (const float*)d_in[8];
    const float* fc_W  = (const float*)d_in[9];
    const float* fc_b  = (const float*)d_in[10];
    float* out = (float*)d_out;

    float *xg, *hseq, *hbuf;
    __nv_bfloat16 *ahi, *alo, *whi, *wlo;
    cudaGetSymbolAddress((void**)&xg, g_xg);
    cudaGetSymbolAddress((void**)&hseq, g_hseq);
    cudaGetSymbolAddress((void**)&hbuf, g_h);
    cudaGetSymbolAddress((void**)&ahi, g_ahi);
    cudaGetSymbolAddress((void**)&alo, g_alo);
    cudaGetSymbolAddress((void**)&whi, g_whi);
    cudaGetSymbolAddress((void**)&wlo, g_wlo);

    cudaFuncSetAttribute(scan_kernel<true>,
                         cudaFuncAttributeMaxDynamicSharedMemorySize, SMEM_SCAN);
    cudaFuncSetAttribute(scan_kernel<false>,
                         cudaFuncAttributeMaxDynamicSharedMemorySize, SMEM_SCAN);
    cudaFuncSetAttribute(gemm_kernel<INDIM>,
                         cudaFuncAttributeMaxDynamicSharedMemorySize, SMEM_GEMM);
    cudaFuncSetAttribute(gemm_kernel<HDIM>,
                         cudaFuncAttributeMaxDynamicSharedMemorySize, SMEM_GEMM);

    const size_t HB = (size_t)BDIM * HDIM;
    const int M = BDIM * TDIM;                 // 32768
    const dim3 ggrid(M / 128, G3 / 128);       // (256, 12)

    // ---- Layer 0 ----
    cvt_split<<<(M * INDIM + 255) / 256, 256>>>(X, ahi, alo, M * INDIM);
    cvt_split<<<(G3 * INDIM + 255) / 256, 256>>>(W_ih0, whi, wlo, G3 * INDIM);
    gemm_kernel<INDIM><<<ggrid, 256, SMEM_GEMM>>>(ahi, alo, whi, wlo, b_ih0, xg);
    init_kernel<<<128, 512>>>(hbuf);
    scan_kernel<true><<<dim3(32, 4), 256, SMEM_SCAN>>>(
        W_hh0, b_hh0, xg, hbuf, hbuf + HB, hseq);

    // ---- Layer 1 ----
    cvt_split<<<(M * HDIM + 255) / 256, 256>>>(hseq, ahi, alo, M * HDIM);
    cvt_split<<<(G3 * HDIM + 255) / 256, 256>>>(W_ih1, whi, wlo, G3 * HDIM);
    gemm_kernel<HDIM><<<ggrid, 256, SMEM_GEMM>>>(ahi, alo, whi, wlo, b_ih1, xg);
    init_kernel<<<128, 512>>>(hbuf);
    scan_kernel<false><<<dim3(32, 4), 256, SMEM_SCAN>>>(
        W_hh1, b_hh1, xg, hbuf, hbuf + HB, nullptr);

    fc_kernel<<<BDIM, 128>>>(hbuf, fc_W, fc_b, out);
}